// round 8
// baseline (speedup 1.0000x reference)
#include <cuda_runtime.h>
#include <math.h>

// Problem constants
#define GROUPS 4
#define NNODE  4096
#define KDIM   128
#define TILE   128
#define NB     (NNODE / TILE)            // 32 block-rows
#define NPAIRS (NB * (NB + 1) / 2)       // 528 upper-triangle block pairs
#define SSTRIDE 132                      // padded smem row stride (floats)

#define SMEM_BYTES (2 * KDIM * SSTRIDE * sizeof(float))   // 135168 B

// sigmoid(x) >= 0.6  =>  x >= ln(1.5) = 0.405465.  0.4f is strictly below,
// and sigmoid(0.4)=0.598688 < 0.6, so the pre-filter can never drop a survivor.
#define XPREFILTER 0.4f

typedef unsigned long long u64;

// ---- f32x2 packed-math helpers (sm_103a; ptxas won't auto-fuse these) ----
__device__ __forceinline__ u64 pack_dup(float a) {
    u64 r; asm("mov.b64 %0, {%1, %1};" : "=l"(r) : "f"(a)); return r;
}
__device__ __forceinline__ void ffma2(u64 &d, u64 a, u64 b) {
    asm("fma.rn.f32x2 %0, %1, %2, %3;" : "=l"(d) : "l"(a), "l"(b), "l"(d));
}
__device__ __forceinline__ float2 unpack2(u64 v) {
    float2 r; asm("mov.b64 {%0, %1}, %2;" : "=f"(r.x), "=f"(r.y) : "l"(v)); return r;
}

// Rare path: accurate sigmoid + threshold in sigmoid-space (matches reference
// comparison exactly). Only called when x > XPREFILTER (~1% of elements).
__device__ __forceinline__ float sig_thresh(float x) {
    const float s = 1.0f / (1.0f + expf(-x));
    return (s < 0.6f) ? 0.0f : s;
}

__global__ __launch_bounds__(256, 1)
void bridge_sgemm_kernel(const float* __restrict__ nodes, float* __restrict__ out)
{
    // ---- map blockIdx.x -> upper-triangle block pair (bi <= bj) ----
    const int t = blockIdx.x;
    int bi = (int)((float)NB + 0.5f - sqrtf(((float)NB + 0.5f) * ((float)NB + 0.5f) - 2.0f * (float)t));
    if (bi < 0) bi = 0;
    if (bi >= NB) bi = NB - 1;
    while (bi + 1 <= NB - 1 && ((bi + 1) * NB - (bi + 1) * bi / 2) <= t) bi++;
    while (bi > 0 && (bi * NB - bi * (bi - 1) / 2) > t) bi--;
    const int bj = bi + (t - (bi * NB - bi * (bi - 1) / 2));

    const int g    = blockIdx.y;
    const int row0 = bi * TILE;
    const int col0 = bj * TILE;
    const bool mirror = (bi != bj);

    const float* __restrict__ A = nodes + (size_t)g * NNODE * KDIM;
    float* __restrict__ C       = out   + (size_t)g * NNODE * (size_t)NNODE;

    extern __shared__ float smem[];
    float* As = smem;                    // [KDIM][SSTRIDE]  k-major (transposed)
    float* Bs = smem + KDIM * SSTRIDE;

    const int tid = threadIdx.x;

    // ---- load both 128x128 fp32 tiles, transposing [m][k] -> [k][m] ----
    {
        const int m  = tid >> 1;
        const int kb = (tid & 1) * 64;
        const float4* arow = (const float4*)(A + (size_t)(row0 + m) * KDIM + kb);
        const float4* brow = (const float4*)(A + (size_t)(col0 + m) * KDIM + kb);
        #pragma unroll
        for (int i = 0; i < 16; i++) {
            const float4 av = arow[i];
            const float4 bv = brow[i];
            const int k = kb + 4 * i;
            As[(k + 0) * SSTRIDE + m] = av.x;
            As[(k + 1) * SSTRIDE + m] = av.y;
            As[(k + 2) * SSTRIDE + m] = av.z;
            As[(k + 3) * SSTRIDE + m] = av.w;
            Bs[(k + 0) * SSTRIDE + m] = bv.x;
            Bs[(k + 1) * SSTRIDE + m] = bv.y;
            Bs[(k + 2) * SSTRIDE + m] = bv.z;
            Bs[(k + 3) * SSTRIDE + m] = bv.w;
        }
    }
    __syncthreads();

    // ---- 8x8 per-thread tile, accumulators packed as f32x2 pairs along j ----
    const int tx = tid & 15;
    const int ty = tid >> 4;

    u64 acc[8][4];
    #pragma unroll
    for (int i = 0; i < 8; i++)
        #pragma unroll
        for (int j = 0; j < 4; j++)
            acc[i][j] = 0ull;

    const float* ap = As + ty * 8;
    const float* bp = Bs + tx * 8;

    #pragma unroll 4
    for (int k = 0; k < KDIM; k++, ap += SSTRIDE, bp += SSTRIDE) {
        // b pairs come straight out of LDS.128 as aligned 64-bit halves
        const ulonglong2 b01 = *(const ulonglong2*)(bp);      // {(b0,b1),(b2,b3)}
        const ulonglong2 b23 = *(const ulonglong2*)(bp + 4);  // {(b4,b5),(b6,b7)}
        u64 bb[4];
        bb[0] = b01.x; bb[1] = b01.y; bb[2] = b23.x; bb[3] = b23.y;

        const float4 a0 = *(const float4*)(ap);
        const float4 a1 = *(const float4*)(ap + 4);
        u64 aa[8];
        aa[0] = pack_dup(a0.x); aa[1] = pack_dup(a0.y);
        aa[2] = pack_dup(a0.z); aa[3] = pack_dup(a0.w);
        aa[4] = pack_dup(a1.x); aa[5] = pack_dup(a1.y);
        aa[6] = pack_dup(a1.z); aa[7] = pack_dup(a1.w);

        #pragma unroll
        for (int i = 0; i < 8; i++)
            #pragma unroll
            for (int j = 0; j < 4; j++)
                ffma2(acc[i][j], aa[i], bb[j]);
    }

    // ---- epilogue: x-space pre-filter (~1% hot), sigmoid only on survivors ----
    float v[8][8];
    #pragma unroll
    for (int i = 0; i < 8; i++) {
        #pragma unroll
        for (int j = 0; j < 4; j++) {
            const float2 p = unpack2(acc[i][j]);
            float r0 = 0.0f, r1 = 0.0f;
            if (p.x > XPREFILTER) r0 = sig_thresh(p.x);
            if (p.y > XPREFILTER) r1 = sig_thresh(p.y);
            v[i][2 * j]     = r0;
            v[i][2 * j + 1] = r1;
        }
    }

    // normal tile: rows row0+ty*8+i, cols col0+tx*8+j
    {
        float* __restrict__ Cbase = C + (size_t)(row0 + ty * 8) * NNODE + (col0 + tx * 8);
        #pragma unroll
        for (int i = 0; i < 8; i++) {
            float4* dst = (float4*)(Cbase + (size_t)i * NNODE);
            dst[0] = make_float4(v[i][0], v[i][1], v[i][2], v[i][3]);
            dst[1] = make_float4(v[i][4], v[i][5], v[i][6], v[i][7]);
        }
    }

    // mirrored tile (C = C^T exactly: same multiply pairs, same k order)
    if (mirror) {
        float* __restrict__ Mbase = C + (size_t)(col0 + tx * 8) * NNODE + (row0 + ty * 8);
        #pragma unroll
        for (int j = 0; j < 8; j++) {
            float4* dst = (float4*)(Mbase + (size_t)j * NNODE);
            dst[0] = make_float4(v[0][j], v[1][j], v[2][j], v[3][j]);
            dst[1] = make_float4(v[4][j], v[5][j], v[6][j], v[7][j]);
        }
    }
}

extern "C" void kernel_launch(void* const* d_in, const int* in_sizes, int n_in,
                              void* d_out, int out_size)
{
    (void)in_sizes; (void)n_in; (void)out_size;
    const float* nodes = (const float*)d_in[0];
    float* out = (float*)d_out;

    static int smem_configured = 0;
    if (!smem_configured) {
        cudaError_t e = cudaFuncSetAttribute(bridge_sgemm_kernel,
                                             cudaFuncAttributeMaxDynamicSharedMemorySize,
                                             (int)SMEM_BYTES);
        if (e == cudaSuccess) smem_configured = 1;
    }

    dim3 grid(NPAIRS, GROUPS);   // 528 block-pairs x 4 groups = 2112 CTAs
    bridge_sgemm_kernel<<<grid, 256, SMEM_BYTES>>>(nodes, out);
}

// round 9
// speedup vs baseline: 1.6090x; 1.6090x over previous
#include <cuda_runtime.h>
#include <math.h>

// Problem constants
#define GROUPS 4
#define NNODE  4096
#define KDIM   128
#define TILE   128
#define NB     (NNODE / TILE)            // 32 block-rows
#define NPAIRS (NB * (NB + 1) / 2)       // 528 upper-triangle block pairs
#define SSTRIDE 132                      // padded smem row stride (floats)

#define SMEM_BYTES (2 * KDIM * SSTRIDE * sizeof(float))   // 135168 B

// sigmoid(x) >= 0.6  =>  x >= ln(1.5) = 0.405465.  0.4f is strictly below,
// and sigmoid(0.4)=0.598688 < 0.6, so the pre-filter can never drop a survivor.
#define XPREFILTER 0.4f

typedef unsigned long long u64;

// ---- f32x2 packed-math helpers (sm_103a; ptxas won't auto-fuse these) ----
__device__ __forceinline__ u64 pack_dup(float a) {
    u64 r; asm("mov.b64 %0, {%1, %1};" : "=l"(r) : "f"(a)); return r;
}
__device__ __forceinline__ void ffma2(u64 &d, u64 a, u64 b) {
    asm("fma.rn.f32x2 %0, %1, %2, %3;" : "=l"(d) : "l"(a), "l"(b), "l"(d));
}
__device__ __forceinline__ float2 unpack2(u64 v) {
    float2 r; asm("mov.b64 {%0, %1}, %2;" : "=f"(r.x), "=f"(r.y) : "l"(v)); return r;
}

// Rare path: accurate sigmoid + threshold in sigmoid-space (matches reference
// comparison exactly). Only reached when x > XPREFILTER (~1% of elements).
__device__ __forceinline__ float sig_thresh(float x) {
    const float s = 1.0f / (1.0f + expf(-x));
    return (s < 0.6f) ? 0.0f : s;
}

__global__ __launch_bounds__(256, 1)
void bridge_sgemm_kernel(const float* __restrict__ nodes, float* __restrict__ out)
{
    // ---- map blockIdx.x -> upper-triangle block pair (bi <= bj) ----
    const int t = blockIdx.x;
    int bi = (int)((float)NB + 0.5f - sqrtf(((float)NB + 0.5f) * ((float)NB + 0.5f) - 2.0f * (float)t));
    if (bi < 0) bi = 0;
    if (bi >= NB) bi = NB - 1;
    while (bi + 1 <= NB - 1 && ((bi + 1) * NB - (bi + 1) * bi / 2) <= t) bi++;
    while (bi > 0 && (bi * NB - bi * (bi - 1) / 2) > t) bi--;
    const int bj = bi + (t - (bi * NB - bi * (bi - 1) / 2));

    const int g    = blockIdx.y;
    const int row0 = bi * TILE;
    const int col0 = bj * TILE;
    const bool mirror = (bi != bj);

    const float* __restrict__ A = nodes + (size_t)g * NNODE * KDIM;
    float* __restrict__ C       = out   + (size_t)g * NNODE * (size_t)NNODE;

    extern __shared__ float smem[];
    float* As = smem;                    // [KDIM][SSTRIDE]  k-major (transposed)
    float* Bs = smem + KDIM * SSTRIDE;

    const int tid = threadIdx.x;

    // ---- load both 128x128 fp32 tiles, transposing [m][k] -> [k][m] ----
    {
        const int m  = tid >> 1;
        const int kb = (tid & 1) * 64;
        const float4* arow = (const float4*)(A + (size_t)(row0 + m) * KDIM + kb);
        const float4* brow = (const float4*)(A + (size_t)(col0 + m) * KDIM + kb);
        #pragma unroll
        for (int i = 0; i < 16; i++) {
            const float4 av = arow[i];
            const float4 bv = brow[i];
            const int k = kb + 4 * i;
            As[(k + 0) * SSTRIDE + m] = av.x;
            As[(k + 1) * SSTRIDE + m] = av.y;
            As[(k + 2) * SSTRIDE + m] = av.z;
            As[(k + 3) * SSTRIDE + m] = av.w;
            Bs[(k + 0) * SSTRIDE + m] = bv.x;
            Bs[(k + 1) * SSTRIDE + m] = bv.y;
            Bs[(k + 2) * SSTRIDE + m] = bv.z;
            Bs[(k + 3) * SSTRIDE + m] = bv.w;
        }
    }
    __syncthreads();

    // ---- 8x8 per-thread tile, accumulators packed as f32x2 pairs along j ----
    const int tx = tid & 15;
    const int ty = tid >> 4;

    u64 acc[8][4];
    #pragma unroll
    for (int i = 0; i < 8; i++)
        #pragma unroll
        for (int j = 0; j < 4; j++)
            acc[i][j] = 0ull;

    const float* ap = As + ty * 8;
    const float* bp = Bs + tx * 8;

    // unroll 2 (NOT 4): unroll 4 overflows the register budget -> local spills
    // (R8 post-mortem: +57% fma-pipe cycles from spill IMADs, +65% L1 traffic)
    #pragma unroll 2
    for (int k = 0; k < KDIM; k++, ap += SSTRIDE, bp += SSTRIDE) {
        // b pairs come straight out of LDS.128 as aligned 64-bit halves
        const ulonglong2 b01 = *(const ulonglong2*)(bp);      // {(b0,b1),(b2,b3)}
        const ulonglong2 b23 = *(const ulonglong2*)(bp + 4);  // {(b4,b5),(b6,b7)}
        u64 bb[4];
        bb[0] = b01.x; bb[1] = b01.y; bb[2] = b23.x; bb[3] = b23.y;

        const float4 a0 = *(const float4*)(ap);
        const float4 a1 = *(const float4*)(ap + 4);
        u64 aa[8];
        aa[0] = pack_dup(a0.x); aa[1] = pack_dup(a0.y);
        aa[2] = pack_dup(a0.z); aa[3] = pack_dup(a0.w);
        aa[4] = pack_dup(a1.x); aa[5] = pack_dup(a1.y);
        aa[6] = pack_dup(a1.z); aa[7] = pack_dup(a1.w);

        #pragma unroll
        for (int i = 0; i < 8; i++)
            #pragma unroll
            for (int j = 0; j < 4; j++)
                ffma2(acc[i][j], aa[i], bb[j]);
    }

    // ---- epilogue: x-space pre-filter (~1% hot), sigmoid only on survivors ----
    float v[8][8];
    #pragma unroll
    for (int i = 0; i < 8; i++) {
        #pragma unroll
        for (int j = 0; j < 4; j++) {
            const float2 p = unpack2(acc[i][j]);
            float r0 = 0.0f, r1 = 0.0f;
            if (p.x > XPREFILTER) r0 = sig_thresh(p.x);
            if (p.y > XPREFILTER) r1 = sig_thresh(p.y);
            v[i][2 * j]     = r0;
            v[i][2 * j + 1] = r1;
        }
    }

    // normal tile: rows row0+ty*8+i, cols col0+tx*8+j
    {
        float* __restrict__ Cbase = C + (size_t)(row0 + ty * 8) * NNODE + (col0 + tx * 8);
        #pragma unroll
        for (int i = 0; i < 8; i++) {
            float4* dst = (float4*)(Cbase + (size_t)i * NNODE);
            dst[0] = make_float4(v[i][0], v[i][1], v[i][2], v[i][3]);
            dst[1] = make_float4(v[i][4], v[i][5], v[i][6], v[i][7]);
        }
    }

    // mirrored tile (C = C^T exactly: same multiply pairs, same k order)
    if (mirror) {
        float* __restrict__ Mbase = C + (size_t)(col0 + tx * 8) * NNODE + (row0 + ty * 8);
        #pragma unroll
        for (int j = 0; j < 8; j++) {
            float4* dst = (float4*)(Mbase + (size_t)j * NNODE);
            dst[0] = make_float4(v[0][j], v[1][j], v[2][j], v[3][j]);
            dst[1] = make_float4(v[4][j], v[5][j], v[6][j], v[7][j]);
        }
    }
}

extern "C" void kernel_launch(void* const* d_in, const int* in_sizes, int n_in,
                              void* d_out, int out_size)
{
    (void)in_sizes; (void)n_in; (void)out_size;
    const float* nodes = (const float*)d_in[0];
    float* out = (float*)d_out;

    static int smem_configured = 0;
    if (!smem_configured) {
        cudaError_t e = cudaFuncSetAttribute(bridge_sgemm_kernel,
                                             cudaFuncAttributeMaxDynamicSharedMemorySize,
                                             (int)SMEM_BYTES);
        if (e == cudaSuccess) smem_configured = 1;
    }

    dim3 grid(NPAIRS, GROUPS);   // 528 block-pairs x 4 groups = 2112 CTAs
    bridge_sgemm_kernel<<<grid, 256, SMEM_BYTES>>>(nodes, out);
}

// round 10
// speedup vs baseline: 1.7202x; 1.0691x over previous
#include <cuda_runtime.h>
#include <math.h>

// Problem constants
#define GROUPS 4
#define NNODE  4096
#define KDIM   128
#define TILE   128
#define NB     (NNODE / TILE)            // 32 block-rows
#define NPAIRS (NB * (NB + 1) / 2)       // 528 upper-triangle block pairs
#define SSTRIDE 132                      // padded smem row stride (floats); 528B = 16B-multiple

#define SMEM_BYTES (2 * KDIM * SSTRIDE * sizeof(float))   // 135168 B

// sigmoid(x) >= 0.6  =>  x >= ln(1.5) = 0.405465.  0.4f is strictly below,
// and sigmoid(0.4)=0.598688 < 0.6, so the pre-filter can never drop a survivor.
#define XPREFILTER 0.4f

typedef unsigned long long u64;

// ---- f32x2 packed-math helpers (sm_103a; ptxas won't auto-fuse these) ----
__device__ __forceinline__ u64 pack_dup(float a) {
    u64 r; asm("mov.b64 %0, {%1, %1};" : "=l"(r) : "f"(a)); return r;
}
__device__ __forceinline__ void ffma2(u64 &d, u64 a, u64 b) {
    asm("fma.rn.f32x2 %0, %1, %2, %3;" : "=l"(d) : "l"(a), "l"(b), "l"(d));
}
__device__ __forceinline__ float2 unpack2(u64 v) {
    float2 r; asm("mov.b64 {%0, %1}, %2;" : "=f"(r.x), "=f"(r.y) : "l"(v)); return r;
}

// Rare path: accurate sigmoid + threshold in sigmoid-space (matches reference
// comparison exactly). Only reached when x > XPREFILTER (~1% of elements).
__device__ __forceinline__ float sig_thresh(float x) {
    const float s = 1.0f / (1.0f + expf(-x));
    return (s < 0.6f) ? 0.0f : s;
}

__global__ __launch_bounds__(256, 1)
void bridge_sgemm_kernel(const float* __restrict__ nodes, float* __restrict__ out)
{
    // ---- map blockIdx.x -> upper-triangle block pair (bi <= bj) ----
    const int t = blockIdx.x;
    int bi = (int)((float)NB + 0.5f - sqrtf(((float)NB + 0.5f) * ((float)NB + 0.5f) - 2.0f * (float)t));
    if (bi < 0) bi = 0;
    if (bi >= NB) bi = NB - 1;
    while (bi + 1 <= NB - 1 && ((bi + 1) * NB - (bi + 1) * bi / 2) <= t) bi++;
    while (bi > 0 && (bi * NB - bi * (bi - 1) / 2) > t) bi--;
    const int bj = bi + (t - (bi * NB - bi * (bi - 1) / 2));

    const int g    = blockIdx.y;
    const int row0 = bi * TILE;
    const int col0 = bj * TILE;
    const bool mirror = (bi != bj);

    const float* __restrict__ A = nodes + (size_t)g * NNODE * KDIM;
    float* __restrict__ C       = out   + (size_t)g * NNODE * (size_t)NNODE;

    extern __shared__ float smem[];
    float* As = smem;                    // [KDIM][SSTRIDE]  k-major (transposed)
    float* Bs = smem + KDIM * SSTRIDE;

    const int tid = threadIdx.x;

    // ---- load both 128x128 fp32 tiles, transposing [m][k] -> [k][m] ----
    {
        const int m  = tid >> 1;
        const int kb = (tid & 1) * 64;
        const float4* arow = (const float4*)(A + (size_t)(row0 + m) * KDIM + kb);
        const float4* brow = (const float4*)(A + (size_t)(col0 + m) * KDIM + kb);
        #pragma unroll
        for (int i = 0; i < 16; i++) {
            const float4 av = arow[i];
            const float4 bv = brow[i];
            const int k = kb + 4 * i;
            As[(k + 0) * SSTRIDE + m] = av.x;
            As[(k + 1) * SSTRIDE + m] = av.y;
            As[(k + 2) * SSTRIDE + m] = av.z;
            As[(k + 3) * SSTRIDE + m] = av.w;
            Bs[(k + 0) * SSTRIDE + m] = bv.x;
            Bs[(k + 1) * SSTRIDE + m] = bv.y;
            Bs[(k + 2) * SSTRIDE + m] = bv.z;
            Bs[(k + 3) * SSTRIDE + m] = bv.w;
        }
    }
    __syncthreads();

    // ---- 8x8 per-thread tile ----
    // b columns per thread: SPLIT fragment {tx*4 .. tx*4+3} and {64+tx*4 .. 64+tx*4+3}.
    // Within a warp the 16 distinct b-addresses are 16B-stride contiguous (256B)
    // -> conflict-free LDS.128 (R9 post-mortem: old tx*8 layout was 4-way conflicted,
    // crossbar ~31K cyc/CTA vs 16K FFMA2 floor).
    const int tx = tid & 15;
    const int ty = tid >> 4;

    u64 acc[8][4];
    #pragma unroll
    for (int i = 0; i < 8; i++)
        #pragma unroll
        for (int j = 0; j < 4; j++)
            acc[i][j] = 0ull;

    const float* ap = As + ty * 8;
    const float* bp = Bs + tx * 4;

    // unroll 2 (NOT 4): unroll 4 overflows the register budget -> local spills
    #pragma unroll 2
    for (int k = 0; k < KDIM; k++, ap += SSTRIDE, bp += SSTRIDE) {
        const ulonglong2 c0 = *(const ulonglong2*)(bp);        // b cols tx*4+0..3
        const ulonglong2 c1 = *(const ulonglong2*)(bp + 64);   // b cols 64+tx*4+0..3
        u64 bb[4];
        bb[0] = c0.x; bb[1] = c0.y; bb[2] = c1.x; bb[3] = c1.y;

        const float4 a0 = *(const float4*)(ap);
        const float4 a1 = *(const float4*)(ap + 4);
        u64 aa[8];
        aa[0] = pack_dup(a0.x); aa[1] = pack_dup(a0.y);
        aa[2] = pack_dup(a0.z); aa[3] = pack_dup(a0.w);
        aa[4] = pack_dup(a1.x); aa[5] = pack_dup(a1.y);
        aa[6] = pack_dup(a1.z); aa[7] = pack_dup(a1.w);

        #pragma unroll
        for (int i = 0; i < 8; i++)
            #pragma unroll
            for (int j = 0; j < 4; j++)
                ffma2(acc[i][j], aa[i], bb[j]);
    }

    // ---- epilogue: x-space pre-filter (~1% hot), sigmoid only on survivors ----
    // v[i][0..3] -> cols col0 + tx*4 + {0..3};  v[i][4..7] -> cols col0 + 64 + tx*4 + {0..3}
    float v[8][8];
    #pragma unroll
    for (int i = 0; i < 8; i++) {
        #pragma unroll
        for (int j = 0; j < 4; j++) {
            const float2 p = unpack2(acc[i][j]);
            float r0 = 0.0f, r1 = 0.0f;
            if (p.x > XPREFILTER) r0 = sig_thresh(p.x);
            if (p.y > XPREFILTER) r1 = sig_thresh(p.y);
            v[i][2 * j]     = r0;      // j<2 -> chunk0, j>=2 -> chunk1 handled below
            v[i][2 * j + 1] = r1;
        }
    }
    // Note: bb[0..1] = chunk0 pairs, bb[2..3] = chunk1 pairs, so
    // v[i][0..3] = chunk0 cols, v[i][4..7] = chunk1 cols. Mapping is consistent.

    // normal tile
    {
        float* __restrict__ Cb0 = C + (size_t)(row0 + ty * 8) * NNODE + (col0 + tx * 4);
        #pragma unroll
        for (int i = 0; i < 8; i++) {
            float* rowp = Cb0 + (size_t)i * NNODE;
            *(float4*)(rowp)      = make_float4(v[i][0], v[i][1], v[i][2], v[i][3]);
            *(float4*)(rowp + 64) = make_float4(v[i][4], v[i][5], v[i][6], v[i][7]);
        }
    }

    // mirrored tile (C = C^T exactly: same multiply pairs, same k order)
    if (mirror) {
        float* __restrict__ Mb0 = C + (size_t)(col0 + tx * 4) * NNODE + (row0 + ty * 8);
        float* __restrict__ Mb1 = C + (size_t)(col0 + 64 + tx * 4) * NNODE + (row0 + ty * 8);
        #pragma unroll
        for (int j = 0; j < 4; j++) {
            float* r0p = Mb0 + (size_t)j * NNODE;
            *(float4*)(r0p)     = make_float4(v[0][j], v[1][j], v[2][j], v[3][j]);
            *(float4*)(r0p + 4) = make_float4(v[4][j], v[5][j], v[6][j], v[7][j]);
            float* r1p = Mb1 + (size_t)j * NNODE;
            *(float4*)(r1p)     = make_float4(v[0][4 + j], v[1][4 + j], v[2][4 + j], v[3][4 + j]);
            *(float4*)(r1p + 4) = make_float4(v[4][4 + j], v[5][4 + j], v[6][4 + j], v[7][4 + j]);
        }
    }
}

extern "C" void kernel_launch(void* const* d_in, const int* in_sizes, int n_in,
                              void* d_out, int out_size)
{
    (void)in_sizes; (void)n_in; (void)out_size;
    const float* nodes = (const float*)d_in[0];
    float* out = (float*)d_out;

    static int smem_configured = 0;
    if (!smem_configured) {
        cudaError_t e = cudaFuncSetAttribute(bridge_sgemm_kernel,
                                             cudaFuncAttributeMaxDynamicSharedMemorySize,
                                             (int)SMEM_BYTES);
        if (e == cudaSuccess) smem_configured = 1;
    }

    dim3 grid(NPAIRS, GROUPS);   // 528 block-pairs x 4 groups = 2112 CTAs
    bridge_sgemm_kernel<<<grid, 256, SMEM_BYTES>>>(nodes, out);
}

// round 12
// speedup vs baseline: 1.7488x; 1.0167x over previous
#include <cuda_runtime.h>
#include <math.h>

// Problem constants
#define GROUPS 4
#define NNODE  4096
#define KDIM   128
#define TILE   128
#define NB     (NNODE / TILE)            // 32 block-rows
#define NPAIRS (NB * (NB + 1) / 2)       // 528 upper-triangle block pairs
#define SSTRIDE 132                      // padded smem row stride (floats)
#define NTHREADS 512                     // 16 warps = 4 per SMSP (R10: 2/SMSP was latency-bound)

#define SMEM_BYTES (2 * KDIM * SSTRIDE * sizeof(float))   // 135168 B

// sigmoid(x) >= 0.6  =>  x >= ln(1.5) = 0.405465.  0.4f is strictly below,
// and sigmoid(0.4)=0.598688 < 0.6, so the pre-filter can never drop a survivor.
#define XPREFILTER 0.4f

typedef unsigned long long u64;

// ---- f32x2 packed-math helpers (sm_103a; ptxas won't auto-fuse these) ----
__device__ __forceinline__ u64 pack_dup(float a) {
    u64 r; asm("mov.b64 %0, {%1, %1};" : "=l"(r) : "f"(a)); return r;
}
__device__ __forceinline__ void ffma2(u64 &d, u64 a, u64 b) {
    asm("fma.rn.f32x2 %0, %1, %2, %3;" : "=l"(d) : "l"(a), "l"(b), "l"(d));
}
__device__ __forceinline__ float2 unpack2(u64 v) {
    float2 r; asm("mov.b64 {%0, %1}, %2;" : "=f"(r.x), "=f"(r.y) : "l"(v)); return r;
}

// Rare path: accurate sigmoid + threshold in sigmoid-space (matches reference
// comparison exactly). Only reached when x > XPREFILTER (~1% of elements).
__device__ __forceinline__ float sig_thresh(float x) {
    const float s = 1.0f / (1.0f + expf(-x));
    return (s < 0.6f) ? 0.0f : s;
}

__global__ __launch_bounds__(NTHREADS, 1)
void bridge_sgemm_kernel(const float* __restrict__ nodes, float* __restrict__ out)
{
    // ---- map blockIdx.x -> upper-triangle block pair (bi <= bj) ----
    const int t = blockIdx.x;
    int bi = (int)((float)NB + 0.5f - sqrtf(((float)NB + 0.5f) * ((float)NB + 0.5f) - 2.0f * (float)t));
    if (bi < 0) bi = 0;
    if (bi >= NB) bi = NB - 1;
    while (bi + 1 <= NB - 1 && ((bi + 1) * NB - (bi + 1) * bi / 2) <= t) bi++;
    while (bi > 0 && (bi * NB - bi * (bi - 1) / 2) > t) bi--;
    const int bj = bi + (t - (bi * NB - bi * (bi - 1) / 2));

    const int g    = blockIdx.y;
    const int row0 = bi * TILE;
    const int col0 = bj * TILE;
    const bool mirror = (bi != bj);

    const float* __restrict__ A = nodes + (size_t)g * NNODE * KDIM;
    float* __restrict__ C       = out   + (size_t)g * NNODE * (size_t)NNODE;

    extern __shared__ float smem[];
    float* As = smem;                    // [KDIM][SSTRIDE]  k-major (transposed)
    float* Bs = smem + KDIM * SSTRIDE;

    const int tid = threadIdx.x;

    // ---- load both 128x128 fp32 tiles, transposing [m][k] -> [k][m] ----
    // 512 threads: m = tid>>2 (0..127), k-chunk = (tid&3)*32; 8 x float4 along k.
    {
        const int m  = tid >> 2;
        const int kb = (tid & 3) * 32;
        const float4* arow = (const float4*)(A + (size_t)(row0 + m) * KDIM + kb);
        const float4* brow = (const float4*)(A + (size_t)(col0 + m) * KDIM + kb);
        #pragma unroll
        for (int i = 0; i < 8; i++) {
            const float4 av = arow[i];
            const float4 bv = brow[i];
            const int k = kb + 4 * i;
            As[(k + 0) * SSTRIDE + m] = av.x;
            As[(k + 1) * SSTRIDE + m] = av.y;
            As[(k + 2) * SSTRIDE + m] = av.z;
            As[(k + 3) * SSTRIDE + m] = av.w;
            Bs[(k + 0) * SSTRIDE + m] = bv.x;
            Bs[(k + 1) * SSTRIDE + m] = bv.y;
            Bs[(k + 2) * SSTRIDE + m] = bv.z;
            Bs[(k + 3) * SSTRIDE + m] = bv.w;
        }
    }
    __syncthreads();

    // ---- 4x8 per-thread tile: 32 row-groups (ty) x 16 col-groups (tx) ----
    // b cols per thread: {tx*4..+3} and {64+tx*4..+3} -> 16B-stride contiguous
    // within a warp -> conflict-free LDS.128. a: 2-address broadcast, ~free.
    const int tx = tid & 15;
    const int ty = tid >> 4;   // 0..31

    u64 acc[4][4];
    #pragma unroll
    for (int i = 0; i < 4; i++)
        #pragma unroll
        for (int j = 0; j < 4; j++)
            acc[i][j] = 0ull;

    const float* ap = As + ty * 4;
    const float* bp = Bs + tx * 4;

    // unroll 4: per-thread footprint is half of the R8 (8x8-tile) attempt that
    // spilled; ~90 regs estimated, safe.
    #pragma unroll 4
    for (int k = 0; k < KDIM; k++, ap += SSTRIDE, bp += SSTRIDE) {
        const ulonglong2 c0 = *(const ulonglong2*)(bp);        // b cols tx*4+0..3
        const ulonglong2 c1 = *(const ulonglong2*)(bp + 64);   // b cols 64+tx*4+0..3
        u64 bb[4];
        bb[0] = c0.x; bb[1] = c0.y; bb[2] = c1.x; bb[3] = c1.y;

        const float4 a0 = *(const float4*)(ap);
        u64 aa[4];
        aa[0] = pack_dup(a0.x); aa[1] = pack_dup(a0.y);
        aa[2] = pack_dup(a0.z); aa[3] = pack_dup(a0.w);

        #pragma unroll
        for (int i = 0; i < 4; i++)
            #pragma unroll
            for (int j = 0; j < 4; j++)
                ffma2(acc[i][j], aa[i], bb[j]);
    }

    // ---- epilogue: x-space pre-filter (~1% hot), sigmoid only on survivors ----
    // v[i][0..3] -> cols col0+tx*4+{0..3}; v[i][4..7] -> cols col0+64+tx*4+{0..3}
    float v[4][8];
    #pragma unroll
    for (int i = 0; i < 4; i++) {
        #pragma unroll
        for (int j = 0; j < 4; j++) {
            const float2 p = unpack2(acc[i][j]);
            float r0 = 0.0f, r1 = 0.0f;
            if (p.x > XPREFILTER) r0 = sig_thresh(p.x);
            if (p.y > XPREFILTER) r1 = sig_thresh(p.y);
            v[i][2 * j]     = r0;
            v[i][2 * j + 1] = r1;
        }
    }

    // normal tile: rows row0 + ty*4 + i
    {
        float* __restrict__ Cb0 = C + (size_t)(row0 + ty * 4) * NNODE + (col0 + tx * 4);
        #pragma unroll
        for (int i = 0; i < 4; i++) {
            float* rowp = Cb0 + (size_t)i * NNODE;
            *(float4*)(rowp)      = make_float4(v[i][0], v[i][1], v[i][2], v[i][3]);
            *(float4*)(rowp + 64) = make_float4(v[i][4], v[i][5], v[i][6], v[i][7]);
        }
    }

    // mirrored tile (C = C^T exactly: same multiply pairs, same k order)
    if (mirror) {
        float* __restrict__ Mb0 = C + (size_t)(col0 + tx * 4) * NNODE + (row0 + ty * 4);
        float* __restrict__ Mb1 = C + (size_t)(col0 + 64 + tx * 4) * NNODE + (row0 + ty * 4);
        #pragma unroll
        for (int j = 0; j < 4; j++) {
            *(float4*)(Mb0 + (size_t)j * NNODE) =
                make_float4(v[0][j], v[1][j], v[2][j], v[3][j]);
            *(float4*)(Mb1 + (size_t)j * NNODE) =
                make_float4(v[0][4 + j], v[1][4 + j], v[2][4 + j], v[3][4 + j]);
        }
    }
}

extern "C" void kernel_launch(void* const* d_in, const int* in_sizes, int n_in,
                              void* d_out, int out_size)
{
    (void)in_sizes; (void)n_in; (void)out_size;
    const float* nodes = (const float*)d_in[0];
    float* out = (float*)d_out;

    static int smem_configured = 0;
    if (!smem_configured) {
        cudaError_t e = cudaFuncSetAttribute(bridge_sgemm_kernel,
                                             cudaFuncAttributeMaxDynamicSharedMemorySize,
                                             (int)SMEM_BYTES);
        if (e == cudaSuccess) smem_configured = 1;
    }

    dim3 grid(NPAIRS, GROUPS);   // 528 block-pairs x 4 groups = 2112 CTAs
    bridge_sgemm_kernel<<<grid, NTHREADS, SMEM_BYTES>>>(nodes, out);
}